// round 14
// baseline (speedup 1.0000x reference)
#include <cuda_runtime.h>
#include <cuda_bf16.h>

#define N        1024
#define ED       256
#define HD       128
#define TSP      64      // pair-tile size

// ---------------- scratch (no allocation allowed) ----------------
__device__ float g_TA[N * 256];          // stage1 partial, e 0..127
__device__ float g_TB[N * 256];          // stage1 partial, e 128..255
__device__ float g_biasf[2 * HD];        // fused biases (q half includes b1)
__device__ float g_qk[N * 256];          // final [qp | kp], bias folded

// ======== kernel L1: T = prev @ [Wq | Wk]  (+ ctx/bias blocks) =============
// blocks 0..255: GEMM tiles nb(8) x i0(16) x splitK(2); blocks 256..263: ctx.
__global__ void __launch_bounds__(128)
stage1_kernel(const float* __restrict__ prev,
              const float* __restrict__ Wq,
              const float* __restrict__ Wk,
              const float* __restrict__ emb,
              const float* __restrict__ Wc,
              const float* __restrict__ bc,
              const float* __restrict__ bq,
              const float* __restrict__ bk,
              const float* __restrict__ b1,
              const float* __restrict__ W1) {
    extern __shared__ float sm[];
    int t = threadIdx.x;
    int blk = blockIdx.x;

    if (blk >= 256) {
        // ---- ctx + 32 bias columns per block (8 blocks) ----
        float* semb = sm;            // 256
        float* sqk  = sm + 256;      // [2][128]
        float* part = sm + 512;      // [4][32]
        int cb = (blk - 256) * 32;
        semb[t] = emb[t];
        semb[t + 128] = emb[t + 128];
        __syncthreads();
        {   // ctx[h]: 256-deep, 8 independent chains, lanes sweep h
            float s[8] = {};
            #pragma unroll
            for (int c = 0; c < 8; c++)
                #pragma unroll 4
                for (int k = 0; k < 32; k++) {
                    int e = c * 32 + k;
                    s[c] = fmaf(semb[e], Wc[e * HD + t], s[c]);
                }
            float v = bc[t] + (((s[0]+s[1])+(s[2]+s[3]))+((s[4]+s[5])+(s[6]+s[7])));
            float ctx = fmaxf(v, 0.f);
            sqk[t] = bq[t] + ctx;
            sqk[HD + t] = bk[t] + ctx;
        }
        __syncthreads();
        {   // bias GEMV for cols [cb, cb+32): 4 partials x 32-deep
            int p = t >> 5;                // 0..3
            int col = cb + (t & 31);
            int half = col >> 7, colh = col & 127;
            float s = 0.f;
            #pragma unroll
            for (int k = 0; k < 32; k++) {
                int kk = p * 32 + k;
                s = fmaf(sqk[half * HD + kk],
                         W1[(half * HD + kk) * HD + colh], s);
            }
            part[p * 32 + (t & 31)] = s;
        }
        __syncthreads();
        if (t < 32) {
            int col = cb + t;
            float s = (col < HD) ? b1[col] : 0.f;
            #pragma unroll
            for (int p = 0; p < 4; p++) s += part[p * 32 + t];
            g_biasf[col] = s;
        }
        return;
    }

    // ---- GEMM tile: T[i0..i0+64, nb..nb+32], K-chunk 128 ----
    float* AsT = sm;                 // [128k][65m]
    float* Bs  = sm + 128 * 65;      // [128k][32n]
    int nb = (blk & 7) * 32;
    int i0 = ((blk >> 3) & 15) * 64;
    int k0 = (blk >> 7) * 128;
    int half = nb >> 7;              // 0 -> Wq cols, 1 -> Wk cols
    int ncol = nb & 127;
    const float* B = half ? Wk : Wq;
    int tx = t & 7, ty = t >> 3;

    #pragma unroll
    for (int l = 0; l < 16; l++) {             // A: 64(m) x 128(k) transposed
        int idx = l * 128 + t;
        int e4 = idx & 31, i = idx >> 5;
        float4 v = *(const float4*)&prev[(i0 + i) * ED + k0 + 4 * e4];
        AsT[(4 * e4 + 0) * 65 + i] = v.x;
        AsT[(4 * e4 + 1) * 65 + i] = v.y;
        AsT[(4 * e4 + 2) * 65 + i] = v.z;
        AsT[(4 * e4 + 3) * 65 + i] = v.w;
    }
    #pragma unroll
    for (int l = 0; l < 8; l++) {              // B: 128(e) x 32 cols
        int idx = l * 128 + t;
        int c4 = idx & 7, row = idx >> 3;
        *(float4*)&Bs[row * 32 + 4 * c4] =
            *(const float4*)&B[(k0 + row) * HD + ncol + 4 * c4];
    }
    __syncthreads();

    float acc[4][4] = {};
    #pragma unroll 4
    for (int k = 0; k < 128; k++) {
        float a0 = AsT[k * 65 + 4 * ty + 0];
        float a1 = AsT[k * 65 + 4 * ty + 1];
        float a2 = AsT[k * 65 + 4 * ty + 2];
        float a3 = AsT[k * 65 + 4 * ty + 3];
        float4 b = *(const float4*)&Bs[k * 32 + 4 * tx];
        acc[0][0] = fmaf(a0, b.x, acc[0][0]); acc[0][1] = fmaf(a0, b.y, acc[0][1]);
        acc[0][2] = fmaf(a0, b.z, acc[0][2]); acc[0][3] = fmaf(a0, b.w, acc[0][3]);
        acc[1][0] = fmaf(a1, b.x, acc[1][0]); acc[1][1] = fmaf(a1, b.y, acc[1][1]);
        acc[1][2] = fmaf(a1, b.z, acc[1][2]); acc[1][3] = fmaf(a1, b.w, acc[1][3]);
        acc[2][0] = fmaf(a2, b.x, acc[2][0]); acc[2][1] = fmaf(a2, b.y, acc[2][1]);
        acc[2][2] = fmaf(a2, b.z, acc[2][2]); acc[2][3] = fmaf(a2, b.w, acc[2][3]);
        acc[3][0] = fmaf(a3, b.x, acc[3][0]); acc[3][1] = fmaf(a3, b.y, acc[3][1]);
        acc[3][2] = fmaf(a3, b.z, acc[3][2]); acc[3][3] = fmaf(a3, b.w, acc[3][3]);
    }
    float* outp = (blk >> 7) ? g_TB : g_TA;
    #pragma unroll
    for (int r = 0; r < 4; r++)
        *(float4*)&outp[(i0 + 4 * ty + r) * 256 + nb + 4 * tx] =
            make_float4(acc[r][0], acc[r][1], acc[r][2], acc[r][3]);
}

// ======== kernel L2: qk = Tsum @ W1(half) + biasf ==========================
// grid (8 n, 16 m), 128 threads, K=128 single pass.
__global__ void __launch_bounds__(128)
stage2_kernel(const float* __restrict__ W1) {
    extern __shared__ float sm[];
    float* AsT = sm;                 // [128k][65m]
    float* Bs  = sm + 128 * 65;      // [128k][32n]
    int nb = blockIdx.x * 32;
    int i0 = blockIdx.y * 64;
    int half = nb >> 7;              // 0: q half (T cols 0..127, W1 top)
    int ncol = nb & 127;
    int t = threadIdx.x, tx = t & 7, ty = t >> 3;

    #pragma unroll
    for (int l = 0; l < 16; l++) {             // A: Tsum 64(m) x 128(k)
        int idx = l * 128 + t;
        int e4 = idx & 31, i = idx >> 5;
        int off = (i0 + i) * 256 + half * HD + 4 * e4;
        float4 a = *(const float4*)&g_TA[off];
        float4 b = *(const float4*)&g_TB[off];
        AsT[(4 * e4 + 0) * 65 + i] = a.x + b.x;
        AsT[(4 * e4 + 1) * 65 + i] = a.y + b.y;
        AsT[(4 * e4 + 2) * 65 + i] = a.z + b.z;
        AsT[(4 * e4 + 3) * 65 + i] = a.w + b.w;
    }
    #pragma unroll
    for (int l = 0; l < 8; l++) {              // B: W1 half, 128 x 32
        int idx = l * 128 + t;
        int c4 = idx & 7, row = idx >> 3;
        *(float4*)&Bs[row * 32 + 4 * c4] =
            *(const float4*)&W1[(half * HD + row) * HD + ncol + 4 * c4];
    }
    __syncthreads();

    float acc[4][4] = {};
    #pragma unroll 4
    for (int k = 0; k < 128; k++) {
        float a0 = AsT[k * 65 + 4 * ty + 0];
        float a1 = AsT[k * 65 + 4 * ty + 1];
        float a2 = AsT[k * 65 + 4 * ty + 2];
        float a3 = AsT[k * 65 + 4 * ty + 3];
        float4 b = *(const float4*)&Bs[k * 32 + 4 * tx];
        acc[0][0] = fmaf(a0, b.x, acc[0][0]); acc[0][1] = fmaf(a0, b.y, acc[0][1]);
        acc[0][2] = fmaf(a0, b.z, acc[0][2]); acc[0][3] = fmaf(a0, b.w, acc[0][3]);
        acc[1][0] = fmaf(a1, b.x, acc[1][0]); acc[1][1] = fmaf(a1, b.y, acc[1][1]);
        acc[1][2] = fmaf(a1, b.z, acc[1][2]); acc[1][3] = fmaf(a1, b.w, acc[1][3]);
        acc[2][0] = fmaf(a2, b.x, acc[2][0]); acc[2][1] = fmaf(a2, b.y, acc[2][1]);
        acc[2][2] = fmaf(a2, b.z, acc[2][2]); acc[2][3] = fmaf(a2, b.w, acc[2][3]);
        acc[3][0] = fmaf(a3, b.x, acc[3][0]); acc[3][1] = fmaf(a3, b.y, acc[3][1]);
        acc[3][2] = fmaf(a3, b.z, acc[3][2]); acc[3][3] = fmaf(a3, b.w, acc[3][3]);
    }
    float b0 = g_biasf[nb + 4 * tx + 0];
    float b1v = g_biasf[nb + 4 * tx + 1];
    float b2v = g_biasf[nb + 4 * tx + 2];
    float b3 = g_biasf[nb + 4 * tx + 3];
    #pragma unroll
    for (int r = 0; r < 4; r++)
        *(float4*)&g_qk[(i0 + 4 * ty + r) * 256 + nb + 4 * tx] =
            make_float4(acc[r][0] + b0, acc[r][1] + b1v,
                        acc[r][2] + b2v, acc[r][3] + b3);
}

// ======== kernel L3: pair scores (R6 body, slim loader) ====================
#define PSTEP(ACC, QP, KP, WP)                                        \
    asm("{\n\t"                                                       \
        ".reg .b64 s; .reg .f32 lo, hi;\n\t"                          \
        "add.rn.f32x2 s, %1, %2;\n\t"                                 \
        "mov.b64 {lo, hi}, s;\n\t"                                    \
        "max.f32 lo, lo, 0f00000000;\n\t"                             \
        "max.f32 hi, hi, 0f00000000;\n\t"                             \
        "mov.b64 s, {lo, hi};\n\t"                                    \
        "fma.rn.f32x2 %0, s, %3, %0;\n\t"                             \
        "}" : "+l"(ACC) : "l"(QP), "l"(KP), "l"(WP))

__global__ void __launch_bounds__(512, 1)
pair_kernel(const float* __restrict__ W2,
            const float* __restrict__ b2,
            float* __restrict__ out) {
    extern __shared__ float sm[];
    float* qs  = sm;                      // [64][128] swizzled
    float* ks  = sm + TSP * HD;           // [64][128] swizzled
    float* w2s = sm + 2 * TSP * HD;       // [128]
    float* red = sm + 2 * TSP * HD + HD;  // [64][65] h-split scratch

    // decode 1D block id -> upper-triangular tile (it <= jt), 16x16 tiles
    int rem = blockIdx.x;
    int it = 0;
    #pragma unroll
    for (int r = 0; r < 16; r++) {
        int len = 16 - r;
        if (rem < len) { it = r; break; }
        rem -= len;
    }
    int jt = it + rem;

    int t = threadIdx.x;
    int ibase = it * TSP, jbase = jt * TSP;

    // loader: single qk buffer (bias already folded); swizzle (i>>2)&7
    {
        int h4 = t & 31;
        #pragma unroll
        for (int l = 0; l < 4; l++) {
            int i = (t >> 5) + 16 * l;
            float4 qv = *(const float4*)&g_qk[(ibase + i) * 256 + 4 * h4];
            float4 kv = *(const float4*)&g_qk[(jbase + i) * 256 + HD + 4 * h4];
            int sw = 4 * (h4 ^ ((i >> 2) & 7));
            *(float4*)&qs[i * HD + sw] = qv;
            *(float4*)&ks[i * HD + sw] = kv;
        }
    }
    if (t < HD) w2s[t] = W2[t];
    __syncthreads();

    int hg = t >> 8;                // h-group: 0 -> h4 0..15, 1 -> 16..31
    int tt = t & 255;
    int tx = tt & 15, ty = tt >> 4;
    int i0 = ty * 4, j0 = tx * 4;
    int swq = ty & 7, swk = tx & 7;

    unsigned long long acc[4][4];
    #pragma unroll
    for (int a = 0; a < 4; a++)
        #pragma unroll
        for (int b = 0; b < 4; b++)
            acc[a][b] = 0ull;

    int h4beg = hg * 16;
    #pragma unroll 2
    for (int hh = 0; hh < 16; hh++) {
        int h4 = h4beg + hh;
        int hq = 4 * (h4 ^ swq);
        int hk = 4 * (h4 ^ swk);
        ulonglong2 q[4], k[4];
        #pragma unroll
        for (int a = 0; a < 4; a++)
            q[a] = *(const ulonglong2*)&qs[(i0 + a) * HD + hq];
        #pragma unroll
        for (int b = 0; b < 4; b++)
            k[b] = *(const ulonglong2*)&ks[(j0 + b) * HD + hk];
        ulonglong2 w = *(const ulonglong2*)&w2s[4 * h4];
        #pragma unroll
        for (int a = 0; a < 4; a++)
            #pragma unroll
            for (int b = 0; b < 4; b++) {
                PSTEP(acc[a][b], q[a].x, k[b].x, w.x);
                PSTEP(acc[a][b], q[a].y, k[b].y, w.y);
            }
    }

    float s[4][4];
    #pragma unroll
    for (int a = 0; a < 4; a++)
        #pragma unroll
        for (int b = 0; b < 4; b++) {
            unsigned long long v = acc[a][b];
            s[a][b] = __int_as_float((unsigned)v) +
                      __int_as_float((unsigned)(v >> 32));
        }

    if (hg) {
        #pragma unroll
        for (int a = 0; a < 4; a++)
            #pragma unroll
            for (int b = 0; b < 4; b++)
                red[(i0 + a) * 65 + j0 + b] = s[a][b];
    }
    __syncthreads();

    if (!hg) {
        float bias = b2[0];
        #pragma unroll
        for (int a = 0; a < 4; a++) {
            int i = ibase + i0 + a;
            int rowoff = i * N - ((i * (i + 1)) >> 1) - i - 1;
            #pragma unroll
            for (int b = 0; b < 4; b++) {
                int j = jbase + j0 + b;
                if (i < j)
                    out[rowoff + j] =
                        s[a][b] + red[(i0 + a) * 65 + j0 + b] + bias;
            }
        }
    }
}

// ---------------- launch ----------------
extern "C" void kernel_launch(void* const* d_in, const int* in_sizes, int n_in,
                              void* d_out, int out_size) {
    const float* emb  = (const float*)d_in[0];
    const float* prev = (const float*)d_in[1];
    const float* Wq   = (const float*)d_in[2];
    const float* bq   = (const float*)d_in[3];
    const float* Wk   = (const float*)d_in[4];
    const float* bk   = (const float*)d_in[5];
    const float* Wc   = (const float*)d_in[6];
    const float* bc   = (const float*)d_in[7];
    const float* W1   = (const float*)d_in[8];
    const float* b1   = (const float*)d_in[9];
    const float* W2   = (const float*)d_in[10];
    const float* b2   = (const float*)d_in[11];
    float* out = (float*)d_out;

    int gemm_smem = (128 * 65 + 128 * 32) * (int)sizeof(float);      // 49664
    int pair_smem = (2 * TSP * HD + HD + 64 * 65) * (int)sizeof(float); // 82688
    cudaFuncSetAttribute(stage1_kernel,
                         cudaFuncAttributeMaxDynamicSharedMemorySize, gemm_smem);
    cudaFuncSetAttribute(stage2_kernel,
                         cudaFuncAttributeMaxDynamicSharedMemorySize, gemm_smem);
    cudaFuncSetAttribute(pair_kernel,
                         cudaFuncAttributeMaxDynamicSharedMemorySize, pair_smem);

    stage1_kernel<<<264, 128, gemm_smem>>>(prev, Wq, Wk, emb, Wc, bc,
                                           bq, bk, b1, W1);
    stage2_kernel<<<dim3(8, 16), 128, gemm_smem>>>(W1);
    pair_kernel<<<136, 512, pair_smem>>>(W2, b2, out);
}

// round 15
// speedup vs baseline: 1.2164x; 1.2164x over previous
#include <cuda_runtime.h>
#include <cuda_bf16.h>

#define N        1024
#define ED       256
#define HD       128
#define TSP      64
#define NB       136            // blocks; all co-resident (<=148 SMs, 1/SM)
#define QK       (N * 256)
#define GSTRIDE  (64 * 65 + 64 * 32)   // 6208 floats per tile-group

// ---------------- scratch (no allocation allowed) ----------------
__device__ float g_T4[4 * QK];           // T = prev@[Wq|Wk], split-K=4 partials
__device__ float g_biasf[2 * HD];        // fused biases (q half includes b1)
__device__ float g_qkA[QK];              // qk partial, h 0..63 (bias folded)
__device__ float g_qkB[QK];              // qk partial, h 64..127
__device__ unsigned g_bar1;
__device__ unsigned g_bar2;

// ticket barrier: monotonic counter, epoch-based; graph-replay safe.
__device__ __forceinline__ void grid_barrier(unsigned* ctr) {
    __syncthreads();
    if (threadIdx.x == 0) {
        __threadfence();
        unsigned ticket = atomicAdd(ctr, 1u);
        unsigned target = (ticket / NB + 1u) * NB;
        while ((int)(*(volatile unsigned*)ctr - target) < 0)
            __nanosleep(20);
        __threadfence();
    }
    __syncthreads();
}

// R6-proven packed step
#define PSTEP(ACC, QP, KP, WP)                                        \
    asm("{\n\t"                                                       \
        ".reg .b64 s; .reg .f32 lo, hi;\n\t"                          \
        "add.rn.f32x2 s, %1, %2;\n\t"                                 \
        "mov.b64 {lo, hi}, s;\n\t"                                    \
        "max.f32 lo, lo, 0f00000000;\n\t"                             \
        "max.f32 hi, hi, 0f00000000;\n\t"                             \
        "mov.b64 s, {lo, hi};\n\t"                                    \
        "fma.rn.f32x2 %0, s, %3, %0;\n\t"                             \
        "}" : "+l"(ACC) : "l"(QP), "l"(KP), "l"(WP))

// 64x32x64 GEMM tile-group body (128 threads), 4x4/thread, one sync.
__device__ __forceinline__ void gemm_tile_64x32(
    float* AsT, float* Bs, int t128, float acc[4][4]) {
    int tx = t128 & 7, ty = t128 >> 3;
    #pragma unroll 4
    for (int k = 0; k < 64; k++) {
        float a0 = AsT[k * 65 + 4 * ty + 0];
        float a1 = AsT[k * 65 + 4 * ty + 1];
        float a2 = AsT[k * 65 + 4 * ty + 2];
        float a3 = AsT[k * 65 + 4 * ty + 3];
        float4 b = *(const float4*)&Bs[k * 32 + 4 * tx];
        acc[0][0] = fmaf(a0, b.x, acc[0][0]); acc[0][1] = fmaf(a0, b.y, acc[0][1]);
        acc[0][2] = fmaf(a0, b.z, acc[0][2]); acc[0][3] = fmaf(a0, b.w, acc[0][3]);
        acc[1][0] = fmaf(a1, b.x, acc[1][0]); acc[1][1] = fmaf(a1, b.y, acc[1][1]);
        acc[1][2] = fmaf(a1, b.z, acc[1][2]); acc[1][3] = fmaf(a1, b.w, acc[1][3]);
        acc[2][0] = fmaf(a2, b.x, acc[2][0]); acc[2][1] = fmaf(a2, b.y, acc[2][1]);
        acc[2][2] = fmaf(a2, b.z, acc[2][2]); acc[2][3] = fmaf(a2, b.w, acc[2][3]);
        acc[3][0] = fmaf(a3, b.x, acc[3][0]); acc[3][1] = fmaf(a3, b.y, acc[3][1]);
        acc[3][2] = fmaf(a3, b.z, acc[3][2]); acc[3][3] = fmaf(a3, b.w, acc[3][3]);
    }
}

__global__ void __launch_bounds__(512, 1)
mono_kernel(const float* __restrict__ emb,
            const float* __restrict__ prev,
            const float* __restrict__ Wq,
            const float* __restrict__ bq,
            const float* __restrict__ Wk,
            const float* __restrict__ bk,
            const float* __restrict__ Wc,
            const float* __restrict__ bc,
            const float* __restrict__ W1,
            const float* __restrict__ b1,
            const float* __restrict__ W2,
            const float* __restrict__ b2,
            float* __restrict__ out) {
    extern __shared__ float sm[];
    int t = threadIdx.x;
    int blk = blockIdx.x;
    int g = t >> 7, t128 = t & 127;
    float* gbase = sm + g * GSTRIDE;

    // ===== PHASE 1 (all input-only): T-GEMM (0-127) || ctxbias (128-135) ===
    if (blk < 128) {
        // T = prev @ [Wq|Wk]: 512 groups = 8n x 16m x 4ksplit, chunk 64
        float* AsT = gbase;
        float* Bs  = gbase + 64 * 65;
        int wg = blk * 4 + g;
        int nb = (wg & 7) * 32;
        int i0 = ((wg >> 3) & 15) * 64;
        int z  = (wg >> 7) & 3;
        int k0 = z * 64;
        int half = nb >> 7;
        int ncol = nb & 127;
        const float* B = half ? Wk : Wq;

        #pragma unroll
        for (int l = 0; l < 8; l++) {          // A: 64(m) x 64(k), transposed
            int idx = l * 128 + t128;
            int e16 = idx & 15, i = idx >> 4;
            float4 v = *(const float4*)&prev[(i0 + i) * ED + k0 + 4 * e16];
            AsT[(4 * e16 + 0) * 65 + i] = v.x;
            AsT[(4 * e16 + 1) * 65 + i] = v.y;
            AsT[(4 * e16 + 2) * 65 + i] = v.z;
            AsT[(4 * e16 + 3) * 65 + i] = v.w;
        }
        #pragma unroll
        for (int l = 0; l < 4; l++) {          // B: 64(e) x 32 cols
            int idx = l * 128 + t128;
            int c4 = idx & 7, row = idx >> 3;
            *(float4*)&Bs[row * 32 + 4 * c4] =
                *(const float4*)&B[(k0 + row) * HD + ncol + 4 * c4];
        }
        __syncthreads();
        float acc[4][4] = {};
        gemm_tile_64x32(AsT, Bs, t128, acc);
        float* outp = g_T4 + z * QK;
        int tx = t128 & 7, ty = t128 >> 3;
        #pragma unroll
        for (int r = 0; r < 4; r++)
            *(float4*)&outp[(i0 + 4 * ty + r) * 256 + nb + 4 * tx] =
                make_float4(acc[r][0], acc[r][1], acc[r][2], acc[r][3]);
    } else {
        // blocks 128-135: ctx + 32 bias columns each (R12-proven, MLP-rich)
        float* semb  = sm;                    // 256
        float* part1 = sm + 256;              // [4][128]
        float* sqk   = sm + 256 + 512;        // [2][128]
        float* part2 = sm + 256 + 512 + 256;  // [16][32]
        int cb = (blk - 128) * 32;
        if (t < 256) semb[t] = emb[t];
        __syncthreads();
        {   // ctx matvec: 4 partials per h, 64-deep as 8 chains of 8
            int p = t >> 7, h = t & 127;
            int kb = p * 64;
            float s[8] = {};
            #pragma unroll
            for (int c = 0; c < 8; c++)
                #pragma unroll
                for (int k = 0; k < 8; k++) {
                    int idx = kb + c * 8 + k;
                    s[c] = fmaf(semb[idx], Wc[idx * HD + h], s[c]);
                }
            part1[p * 128 + h] = ((s[0]+s[1])+(s[2]+s[3]))+((s[4]+s[5])+(s[6]+s[7]));
        }
        __syncthreads();
        if (t < 128) {
            float v = bc[t] + part1[t] + part1[128 + t] + part1[256 + t] + part1[384 + t];
            float ctx = fmaxf(v, 0.f);
            sqk[t] = bq[t] + ctx;
            sqk[128 + t] = bk[t] + ctx;
        }
        __syncthreads();
        {   // bias GEMV for 32 cols: 16 partials per col, 8-deep each
            int col = cb + (t & 31);
            int p = t >> 5;                   // 0..15
            int half = col >> 7, colh = col & 127;
            float s = 0.f;
            #pragma unroll
            for (int k = 0; k < 8; k++) {
                int kk = p * 8 + k;
                s = fmaf(sqk[half * 128 + kk],
                         W1[(half * HD + kk) * HD + colh], s);
            }
            part2[p * 32 + (t & 31)] = s;
        }
        __syncthreads();
        if (t < 32) {
            int col = cb + t;
            float s = (col < HD) ? b1[col] : 0.f;
            #pragma unroll
            for (int p = 0; p < 16; p++) s += part2[p * 32 + t];
            g_biasf[col] = s;
        }
    }

    grid_barrier(&g_bar1);

    // ===== PHASE 2: qk = Tsum @ blockdiag(W1) + biasf ======================
    // 256 groups = 8n x 16m x 2ksplit (chunk 64 of the 128-deep h sum)
    if (blk < 64) {
        float* AsT = gbase;
        float* Bs  = gbase + 64 * 65;
        int wg = blk * 4 + g;          // 0..255
        int nb = (wg & 7) * 32;
        int i0 = ((wg >> 3) & 15) * 64;
        int z2 = (wg >> 7) & 1;
        int half = nb >> 7;
        int ncol = nb & 127;
        int kb = half * HD + z2 * 64;  // column base in T / row base in W1

        #pragma unroll
        for (int l = 0; l < 8; l++) {          // A: Tsum 64(m) x 64(k)
            int idx = l * 128 + t128;
            int e16 = idx & 15, i = idx >> 4;
            int off = (i0 + i) * 256 + kb + 4 * e16;
            float4 v0 = *(const float4*)&g_T4[off];
            float4 v1 = *(const float4*)&g_T4[QK + off];
            float4 v2 = *(const float4*)&g_T4[2 * QK + off];
            float4 v3 = *(const float4*)&g_T4[3 * QK + off];
            AsT[(4 * e16 + 0) * 65 + i] = (v0.x + v1.x) + (v2.x + v3.x);
            AsT[(4 * e16 + 1) * 65 + i] = (v0.y + v1.y) + (v2.y + v3.y);
            AsT[(4 * e16 + 2) * 65 + i] = (v0.z + v1.z) + (v2.z + v3.z);
            AsT[(4 * e16 + 3) * 65 + i] = (v0.w + v1.w) + (v2.w + v3.w);
        }
        #pragma unroll
        for (int l = 0; l < 4; l++) {          // B: W1 rows kb..kb+64, 32 cols
            int idx = l * 128 + t128;
            int c4 = idx & 7, row = idx >> 3;
            *(float4*)&Bs[row * 32 + 4 * c4] =
                *(const float4*)&W1[(kb + row) * HD + ncol + 4 * c4];
        }
        __syncthreads();
        float acc[4][4] = {};
        gemm_tile_64x32(AsT, Bs, t128, acc);
        int tx = t128 & 7, ty = t128 >> 3;
        float b0 = 0.f, b1v = 0.f, b2v = 0.f, b3 = 0.f;
        if (z2 == 0) {                 // fold bias into first partial
            b0 = g_biasf[nb + 4 * tx + 0];
            b1v = g_biasf[nb + 4 * tx + 1];
            b2v = g_biasf[nb + 4 * tx + 2];
            b3 = g_biasf[nb + 4 * tx + 3];
        }
        float* outp = z2 ? g_qkB : g_qkA;
        #pragma unroll
        for (int r = 0; r < 4; r++)
            *(float4*)&outp[(i0 + 4 * ty + r) * 256 + nb + 4 * tx] =
                make_float4(acc[r][0] + b0, acc[r][1] + b1v,
                            acc[r][2] + b2v, acc[r][3] + b3);
    }

    grid_barrier(&g_bar2);

    // ===== PHASE 3: pair scores (R6 body + R6 loader) ======================
    {
        float* qs  = sm;
        float* ks  = sm + TSP * HD;
        float* w2s = sm + 2 * TSP * HD;
        float* red = sm + 2 * TSP * HD + HD;  // [64][65]

        int rem = blk;
        int it = 0;
        #pragma unroll
        for (int r = 0; r < 16; r++) {
            int len = 16 - r;
            if (rem < len) { it = r; break; }
            rem -= len;
        }
        int jt = it + rem;
        int ibase = it * TSP, jbase = jt * TSP;

        {   // loader: sum 2 partials (bias already folded); swizzle (i>>2)&7
            int h4 = t & 31;
            #pragma unroll
            for (int l = 0; l < 4; l++) {
                int i = (t >> 5) + 16 * l;
                int qo = (ibase + i) * 256 + 4 * h4;
                int ko = (jbase + i) * 256 + HD + 4 * h4;
                float4 qa = *(const float4*)&g_qkA[qo];
                float4 qb = *(const float4*)&g_qkB[qo];
                float4 ka = *(const float4*)&g_qkA[ko];
                float4 kb = *(const float4*)&g_qkB[ko];
                float4 qv = make_float4(qa.x + qb.x, qa.y + qb.y,
                                        qa.z + qb.z, qa.w + qb.w);
                float4 kv = make_float4(ka.x + kb.x, ka.y + kb.y,
                                        ka.z + kb.z, ka.w + kb.w);
                int sw = 4 * (h4 ^ ((i >> 2) & 7));
                *(float4*)&qs[i * HD + sw] = qv;
                *(float4*)&ks[i * HD + sw] = kv;
            }
        }
        if (t < HD) w2s[t] = W2[t];
        __syncthreads();

        int hg = t >> 8;
        int tt = t & 255;
        int tx = tt & 15, ty = tt >> 4;
        int i0 = ty * 4, j0 = tx * 4;
        int swq = ty & 7, swk = tx & 7;

        unsigned long long acc[4][4];
        #pragma unroll
        for (int a = 0; a < 4; a++)
            #pragma unroll
            for (int b = 0; b < 4; b++)
                acc[a][b] = 0ull;

        int h4beg = hg * 16;
        #pragma unroll 2
        for (int hh = 0; hh < 16; hh++) {
            int h4 = h4beg + hh;
            int hq = 4 * (h4 ^ swq);
            int hk = 4 * (h4 ^ swk);
            ulonglong2 q[4], k[4];
            #pragma unroll
            for (int a = 0; a < 4; a++)
                q[a] = *(const ulonglong2*)&qs[(i0 + a) * HD + hq];
            #pragma unroll
            for (int b = 0; b < 4; b++)
                k[b] = *(const ulonglong2*)&ks[(j0 + b) * HD + hk];
            ulonglong2 w = *(const ulonglong2*)&w2s[4 * h4];
            #pragma unroll
            for (int a = 0; a < 4; a++)
                #pragma unroll
                for (int b = 0; b < 4; b++) {
                    PSTEP(acc[a][b], q[a].x, k[b].x, w.x);
                    PSTEP(acc[a][b], q[a].y, k[b].y, w.y);
                }
        }

        float s[4][4];
        #pragma unroll
        for (int a = 0; a < 4; a++)
            #pragma unroll
            for (int b = 0; b < 4; b++) {
                unsigned long long v = acc[a][b];
                s[a][b] = __int_as_float((unsigned)v) +
                          __int_as_float((unsigned)(v >> 32));
            }

        if (hg) {
            #pragma unroll
            for (int a = 0; a < 4; a++)
                #pragma unroll
                for (int b = 0; b < 4; b++)
                    red[(i0 + a) * 65 + j0 + b] = s[a][b];
        }
        __syncthreads();

        if (!hg) {
            float bias = b2[0];
            #pragma unroll
            for (int a = 0; a < 4; a++) {
                int i = ibase + i0 + a;
                int rowoff = i * N - ((i * (i + 1)) >> 1) - i - 1;
                #pragma unroll
                for (int b = 0; b < 4; b++) {
                    int j = jbase + j0 + b;
                    if (i < j)
                        out[rowoff + j] =
                            s[a][b] + red[(i0 + a) * 65 + j0 + b] + bias;
                }
            }
        }
    }
}

// ---------------- launch ----------------
extern "C" void kernel_launch(void* const* d_in, const int* in_sizes, int n_in,
                              void* d_out, int out_size) {
    const float* emb  = (const float*)d_in[0];
    const float* prev = (const float*)d_in[1];
    const float* Wq   = (const float*)d_in[2];
    const float* bq   = (const float*)d_in[3];
    const float* Wk   = (const float*)d_in[4];
    const float* bk   = (const float*)d_in[5];
    const float* Wc   = (const float*)d_in[6];
    const float* bc   = (const float*)d_in[7];
    const float* W1   = (const float*)d_in[8];
    const float* b1   = (const float*)d_in[9];
    const float* W2   = (const float*)d_in[10];
    const float* b2   = (const float*)d_in[11];
    float* out = (float*)d_out;

    int smem = 4 * GSTRIDE * (int)sizeof(float);   // 99328 (covers all phases)
    cudaFuncSetAttribute(mono_kernel,
                         cudaFuncAttributeMaxDynamicSharedMemorySize, smem);

    mono_kernel<<<NB, 512, smem>>>(emb, prev, Wq, bq, Wk, bk, Wc, bc,
                                   W1, b1, W2, b2, out);
}

// round 16
// speedup vs baseline: 1.2786x; 1.0511x over previous
#include <cuda_runtime.h>
#include <cuda_bf16.h>

#define N        1024
#define ED       256
#define HD       128
#define TSP      64
#define NB       136            // blocks; all co-resident (<=148 SMs, 1/SM)
#define QK       (N * 256)
#define GSTRIDE  (64 * 65 + 64 * 32)   // 6208 floats per tile-group

// ---------------- scratch (no allocation allowed) ----------------
__device__ float g_T4[4 * QK];           // T = prev@[Wq|Wk], split-K=4 partials
__device__ float g_biasf[2 * HD];        // fused biases (q half includes b1)
__device__ float g_qkA[QK];              // qk partial, h 0..63 (bias folded)
__device__ float g_qkB[QK];              // qk partial, h 64..127
__device__ unsigned g_bar1;
__device__ unsigned g_bar2;

// ticket barrier: monotonic counter, epoch-based; graph-replay safe.
__device__ __forceinline__ void grid_barrier(unsigned* ctr) {
    __syncthreads();
    if (threadIdx.x == 0) {
        __threadfence();
        unsigned ticket = atomicAdd(ctr, 1u);
        unsigned target = (ticket / NB + 1u) * NB;
        while ((int)(*(volatile unsigned*)ctr - target) < 0)
            __nanosleep(20);
        __threadfence();
    }
    __syncthreads();
}

// R6-proven packed step
#define PSTEP(ACC, QP, KP, WP)                                        \
    asm("{\n\t"                                                       \
        ".reg .b64 s; .reg .f32 lo, hi;\n\t"                          \
        "add.rn.f32x2 s, %1, %2;\n\t"                                 \
        "mov.b64 {lo, hi}, s;\n\t"                                    \
        "max.f32 lo, lo, 0f00000000;\n\t"                             \
        "max.f32 hi, hi, 0f00000000;\n\t"                             \
        "mov.b64 s, {lo, hi};\n\t"                                    \
        "fma.rn.f32x2 %0, s, %3, %0;\n\t"                             \
        "}" : "+l"(ACC) : "l"(QP), "l"(KP), "l"(WP))

// 64x32x64 GEMM tile body, software-pipelined (double-buffered regs).
__device__ __forceinline__ void gemm_tile_64x32_pipe(
    const float* AsT, const float* Bs, int t128, float acc[4][4]) {
    int tx = t128 & 7, ty = t128 >> 3;
    float a_cur0 = AsT[4 * ty + 0];
    float a_cur1 = AsT[4 * ty + 1];
    float a_cur2 = AsT[4 * ty + 2];
    float a_cur3 = AsT[4 * ty + 3];
    float4 b_cur = *(const float4*)&Bs[4 * tx];
    #pragma unroll
    for (int k = 0; k < 64; k++) {
        float a0 = a_cur0, a1 = a_cur1, a2 = a_cur2, a3 = a_cur3;
        float4 b = b_cur;
        if (k < 63) {
            a_cur0 = AsT[(k + 1) * 65 + 4 * ty + 0];
            a_cur1 = AsT[(k + 1) * 65 + 4 * ty + 1];
            a_cur2 = AsT[(k + 1) * 65 + 4 * ty + 2];
            a_cur3 = AsT[(k + 1) * 65 + 4 * ty + 3];
            b_cur  = *(const float4*)&Bs[(k + 1) * 32 + 4 * tx];
        }
        acc[0][0] = fmaf(a0, b.x, acc[0][0]); acc[0][1] = fmaf(a0, b.y, acc[0][1]);
        acc[0][2] = fmaf(a0, b.z, acc[0][2]); acc[0][3] = fmaf(a0, b.w, acc[0][3]);
        acc[1][0] = fmaf(a1, b.x, acc[1][0]); acc[1][1] = fmaf(a1, b.y, acc[1][1]);
        acc[1][2] = fmaf(a1, b.z, acc[1][2]); acc[1][3] = fmaf(a1, b.w, acc[1][3]);
        acc[2][0] = fmaf(a2, b.x, acc[2][0]); acc[2][1] = fmaf(a2, b.y, acc[2][1]);
        acc[2][2] = fmaf(a2, b.z, acc[2][2]); acc[2][3] = fmaf(a2, b.w, acc[2][3]);
        acc[3][0] = fmaf(a3, b.x, acc[3][0]); acc[3][1] = fmaf(a3, b.y, acc[3][1]);
        acc[3][2] = fmaf(a3, b.z, acc[3][2]); acc[3][3] = fmaf(a3, b.w, acc[3][3]);
    }
}

__global__ void __launch_bounds__(512, 1)
mono_kernel(const float* __restrict__ emb,
            const float* __restrict__ prev,
            const float* __restrict__ Wq,
            const float* __restrict__ bq,
            const float* __restrict__ Wk,
            const float* __restrict__ bk,
            const float* __restrict__ Wc,
            const float* __restrict__ bc,
            const float* __restrict__ W1,
            const float* __restrict__ b1,
            const float* __restrict__ W2,
            const float* __restrict__ b2,
            float* __restrict__ out) {
    extern __shared__ float sm[];
    int t = threadIdx.x;
    int blk = blockIdx.x;
    int g = t >> 7, t128 = t & 127;
    float* gbase = sm + g * GSTRIDE;

    // ===== PHASE 1 (all input-only): T-GEMM (0-127) || ctxbias (128-135) ===
    if (blk < 128) {
        // T = prev @ [Wq|Wk]: 512 groups = 8n x 16m x 4ksplit, chunk 64
        float* AsT = gbase;
        float* Bs  = gbase + 64 * 65;
        int wg = blk * 4 + g;
        int nb = (wg & 7) * 32;
        int i0 = ((wg >> 3) & 15) * 64;
        int z  = (wg >> 7) & 3;
        int k0 = z * 64;
        int half = nb >> 7;
        int ncol = nb & 127;
        const float* B = half ? Wk : Wq;

        #pragma unroll
        for (int l = 0; l < 8; l++) {          // A: 64(m) x 64(k), transposed
            int idx = l * 128 + t128;
            int e16 = idx & 15, i = idx >> 4;
            float4 v = *(const float4*)&prev[(i0 + i) * ED + k0 + 4 * e16];
            AsT[(4 * e16 + 0) * 65 + i] = v.x;
            AsT[(4 * e16 + 1) * 65 + i] = v.y;
            AsT[(4 * e16 + 2) * 65 + i] = v.z;
            AsT[(4 * e16 + 3) * 65 + i] = v.w;
        }
        #pragma unroll
        for (int l = 0; l < 4; l++) {          // B: 64(e) x 32 cols
            int idx = l * 128 + t128;
            int c4 = idx & 7, row = idx >> 3;
            *(float4*)&Bs[row * 32 + 4 * c4] =
                *(const float4*)&B[(k0 + row) * HD + ncol + 4 * c4];
        }
        __syncthreads();
        float acc[4][4] = {};
        gemm_tile_64x32_pipe(AsT, Bs, t128, acc);
        float* outp = g_T4 + z * QK;
        int tx = t128 & 7, ty = t128 >> 3;
        #pragma unroll
        for (int r = 0; r < 4; r++)
            *(float4*)&outp[(i0 + 4 * ty + r) * 256 + nb + 4 * tx] =
                make_float4(acc[r][0], acc[r][1], acc[r][2], acc[r][3]);
    } else {
        // blocks 128-135: ctx + 32 bias columns each (R12-proven, MLP-rich)
        float* semb  = sm;                    // 256
        float* part1 = sm + 256;              // [4][128]
        float* sqk   = sm + 256 + 512;        // [2][128]
        float* part2 = sm + 256 + 512 + 256;  // [16][32]
        int cb = (blk - 128) * 32;
        if (t < 256) semb[t] = emb[t];
        __syncthreads();
        {   // ctx matvec: 4 partials per h, 64-deep as 8 chains of 8
            int p = t >> 7, h = t & 127;
            int kb = p * 64;
            float s[8] = {};
            #pragma unroll
            for (int c = 0; c < 8; c++)
                #pragma unroll
                for (int k = 0; k < 8; k++) {
                    int idx = kb + c * 8 + k;
                    s[c] = fmaf(semb[idx], Wc[idx * HD + h], s[c]);
                }
            part1[p * 128 + h] = ((s[0]+s[1])+(s[2]+s[3]))+((s[4]+s[5])+(s[6]+s[7]));
        }
        __syncthreads();
        if (t < 128) {
            float v = bc[t] + part1[t] + part1[128 + t] + part1[256 + t] + part1[384 + t];
            float ctx = fmaxf(v, 0.f);
            sqk[t] = bq[t] + ctx;
            sqk[128 + t] = bk[t] + ctx;
        }
        __syncthreads();
        {   // bias GEMV for 32 cols: 16 partials per col, 8-deep each
            int col = cb + (t & 31);
            int p = t >> 5;                   // 0..15
            int half = col >> 7, colh = col & 127;
            float s = 0.f;
            #pragma unroll
            for (int k = 0; k < 8; k++) {
                int kk = p * 8 + k;
                s = fmaf(sqk[half * 128 + kk],
                         W1[(half * HD + kk) * HD + colh], s);
            }
            part2[p * 32 + (t & 31)] = s;
        }
        __syncthreads();
        if (t < 32) {
            int col = cb + t;
            float s = (col < HD) ? b1[col] : 0.f;
            #pragma unroll
            for (int p = 0; p < 16; p++) s += part2[p * 32 + t];
            g_biasf[col] = s;
        }
    }

    grid_barrier(&g_bar1);

    // ===== PHASE 2: qk = Tsum @ blockdiag(W1) + biasf ======================
    // 256 groups = 8n x 16m x 2ksplit (chunk 64 of the 128-deep h sum)
    if (blk < 64) {
        float* AsT = gbase;
        float* Bs  = gbase + 64 * 65;
        int wg = blk * 4 + g;          // 0..255
        int nb = (wg & 7) * 32;
        int i0 = ((wg >> 3) & 15) * 64;
        int z2 = (wg >> 7) & 1;
        int half = nb >> 7;
        int ncol = nb & 127;
        int kb = half * HD + z2 * 64;  // column base in T / row base in W1

        #pragma unroll
        for (int l = 0; l < 8; l++) {          // A: Tsum 64(m) x 64(k)
            int idx = l * 128 + t128;
            int e16 = idx & 15, i = idx >> 4;
            int off = (i0 + i) * 256 + kb + 4 * e16;
            float4 v0 = *(const float4*)&g_T4[off];
            float4 v1 = *(const float4*)&g_T4[QK + off];
            float4 v2 = *(const float4*)&g_T4[2 * QK + off];
            float4 v3 = *(const float4*)&g_T4[3 * QK + off];
            AsT[(4 * e16 + 0) * 65 + i] = (v0.x + v1.x) + (v2.x + v3.x);
            AsT[(4 * e16 + 1) * 65 + i] = (v0.y + v1.y) + (v2.y + v3.y);
            AsT[(4 * e16 + 2) * 65 + i] = (v0.z + v1.z) + (v2.z + v3.z);
            AsT[(4 * e16 + 3) * 65 + i] = (v0.w + v1.w) + (v2.w + v3.w);
        }
        #pragma unroll
        for (int l = 0; l < 4; l++) {          // B: W1 rows kb..kb+64, 32 cols
            int idx = l * 128 + t128;
            int c4 = idx & 7, row = idx >> 3;
            *(float4*)&Bs[row * 32 + 4 * c4] =
                *(const float4*)&W1[(kb + row) * HD + ncol + 4 * c4];
        }
        __syncthreads();
        float acc[4][4] = {};
        gemm_tile_64x32_pipe(AsT, Bs, t128, acc);
        int tx = t128 & 7, ty = t128 >> 3;
        float b0 = 0.f, b1v = 0.f, b2v = 0.f, b3 = 0.f;
        if (z2 == 0) {                 // fold bias into first partial
            b0 = g_biasf[nb + 4 * tx + 0];
            b1v = g_biasf[nb + 4 * tx + 1];
            b2v = g_biasf[nb + 4 * tx + 2];
            b3 = g_biasf[nb + 4 * tx + 3];
        }
        float* outp = z2 ? g_qkB : g_qkA;
        #pragma unroll
        for (int r = 0; r < 4; r++)
            *(float4*)&outp[(i0 + 4 * ty + r) * 256 + nb + 4 * tx] =
                make_float4(acc[r][0] + b0, acc[r][1] + b1v,
                            acc[r][2] + b2v, acc[r][3] + b3);
    }

    grid_barrier(&g_bar2);

    // ===== PHASE 3: pair scores (R6 body + loader) =========================
    {
        float* qs  = sm;
        float* ks  = sm + TSP * HD;
        float* w2s = sm + 2 * TSP * HD;
        float* red = sm + 2 * TSP * HD + HD;  // [64][65]

        int rem = blk;
        int it = 0;
        #pragma unroll
        for (int r = 0; r < 16; r++) {
            int len = 16 - r;
            if (rem < len) { it = r; break; }
            rem -= len;
        }
        int jt = it + rem;
        int ibase = it * TSP, jbase = jt * TSP;

        {   // loader: sum 2 partials (bias already folded); swizzle (i>>2)&7
            int h4 = t & 31;
            #pragma unroll
            for (int l = 0; l < 4; l++) {
                int i = (t >> 5) + 16 * l;
                int qo = (ibase + i) * 256 + 4 * h4;
                int ko = (jbase + i) * 256 + HD + 4 * h4;
                float4 qa = *(const float4*)&g_qkA[qo];
                float4 qb = *(const float4*)&g_qkB[qo];
                float4 ka = *(const float4*)&g_qkA[ko];
                float4 kb = *(const float4*)&g_qkB[ko];
                float4 qv = make_float4(qa.x + qb.x, qa.y + qb.y,
                                        qa.z + qb.z, qa.w + qb.w);
                float4 kv = make_float4(ka.x + kb.x, ka.y + kb.y,
                                        ka.z + kb.z, ka.w + kb.w);
                int sw = 4 * (h4 ^ ((i >> 2) & 7));
                *(float4*)&qs[i * HD + sw] = qv;
                *(float4*)&ks[i * HD + sw] = kv;
            }
        }
        if (t < HD) w2s[t] = W2[t];
        __syncthreads();

        int hg = t >> 8;
        int tt = t & 255;
        int tx = tt & 15, ty = tt >> 4;
        int i0 = ty * 4, j0 = tx * 4;
        int swq = ty & 7, swk = tx & 7;

        unsigned long long acc[4][4];
        #pragma unroll
        for (int a = 0; a < 4; a++)
            #pragma unroll
            for (int b = 0; b < 4; b++)
                acc[a][b] = 0ull;

        int h4beg = hg * 16;
        #pragma unroll 2
        for (int hh = 0; hh < 16; hh++) {
            int h4 = h4beg + hh;
            int hq = 4 * (h4 ^ swq);
            int hk = 4 * (h4 ^ swk);
            ulonglong2 q[4], k[4];
            #pragma unroll
            for (int a = 0; a < 4; a++)
                q[a] = *(const ulonglong2*)&qs[(i0 + a) * HD + hq];
            #pragma unroll
            for (int b = 0; b < 4; b++)
                k[b] = *(const ulonglong2*)&ks[(j0 + b) * HD + hk];
            ulonglong2 w = *(const ulonglong2*)&w2s[4 * h4];
            #pragma unroll
            for (int a = 0; a < 4; a++)
                #pragma unroll
                for (int b = 0; b < 4; b++) {
                    PSTEP(acc[a][b], q[a].x, k[b].x, w.x);
                    PSTEP(acc[a][b], q[a].y, k[b].y, w.y);
                }
        }

        float s[4][4];
        #pragma unroll
        for (int a = 0; a < 4; a++)
            #pragma unroll
            for (int b = 0; b < 4; b++) {
                unsigned long long v = acc[a][b];
                s[a][b] = __int_as_float((unsigned)v) +
                          __int_as_float((unsigned)(v >> 32));
            }

        if (hg) {
            #pragma unroll
            for (int a = 0; a < 4; a++)
                #pragma unroll
                for (int b = 0; b < 4; b++)
                    red[(i0 + a) * 65 + j0 + b] = s[a][b];
        }
        __syncthreads();

        if (!hg) {
            float bias = b2[0];
            #pragma unroll
            for (int a = 0; a < 4; a++) {
                int i = ibase + i0 + a;
                int rowoff = i * N - ((i * (i + 1)) >> 1) - i - 1;
                #pragma unroll
                for (int b = 0; b < 4; b++) {
                    int j = jbase + j0 + b;
                    if (i < j)
                        out[rowoff + j] =
                            s[a][b] + red[(i0 + a) * 65 + j0 + b] + bias;
                }
            }
        }
    }
}

// ---------------- launch ----------------
extern "C" void kernel_launch(void* const* d_in, const int* in_sizes, int n_in,
                              void* d_out, int out_size) {
    const float* emb  = (const float*)d_in[0];
    const float* prev = (const float*)d_in[1];
    const float* Wq   = (const float*)d_in[2];
    const float* bq   = (const float*)d_in[3];
    const float* Wk   = (const float*)d_in[4];
    const float* bk   = (const float*)d_in[5];
    const float* Wc   = (const float*)d_in[6];
    const float* bc   = (const float*)d_in[7];
    const float* W1   = (const float*)d_in[8];
    const float* b1   = (const float*)d_in[9];
    const float* W2   = (const float*)d_in[10];
    const float* b2   = (const float*)d_in[11];
    float* out = (float*)d_out;

    int smem = 4 * GSTRIDE * (int)sizeof(float);   // 99328 (covers all phases)
    cudaFuncSetAttribute(mono_kernel,
                         cudaFuncAttributeMaxDynamicSharedMemorySize, smem);

    mono_kernel<<<NB, 512, smem>>>(emb, prev, Wq, bq, Wk, bk, Wc, bc,
                                   W1, b1, W2, b2, out);
}